// round 1
// baseline (speedup 1.0000x reference)
#include <cuda_runtime.h>

// SegGPS_66949950210076
// out[b] = sum_m prod_l eps[idx[b,l], m, l, nup[b,l], ndn[b,l]]
// B=8192, L=64, M=64, LOCAL_DIM=4, eps shape (4,64,64,65,65) fp32.

#define B_SZ 8192
#define L_SZ 64
#define M_SZ 64
#define IDX_STRIDE 17305600   // M*L*65*65
#define M_STRIDE   270400     // L*65*65
#define L_STRIDE   4225       // 65*65

__device__ int g_is_int64;

__global__ void detect_reset_kernel() { g_is_int64 = 1; }

// Indices are logically int64 in the reference, but JAX default (x64 off)
// produces int32. Detect: under int64 little-endian, every odd 32-bit word
// of the buffer is 0 (values are in [0,4)). Under int32, odd words are
// random indices in [0,4) (25% zero each) -> virtually impossible to be all
// zero over 262k samples. Only scan the first n 32-bit words, which is
// in-bounds under either interpretation.
__global__ void detect_kernel(const unsigned* __restrict__ w, int n_pairs) {
    int i = blockIdx.x * blockDim.x + threadIdx.x;
    if (i < n_pairs) {
        if (w[2 * i + 1] != 0u) g_is_int64 = 0;   // racy benign: all write 0
    }
}

__global__ __launch_bounds__(64) void seggps_kernel(
    const void*  __restrict__ idx_raw,
    const float* __restrict__ eps,
    float*       __restrict__ out)
{
    __shared__ int   offs[L_SZ];
    __shared__ int   wu, wd;
    __shared__ float wsum0;

    const int t    = threadIdx.x;        // t = m for the gather phase, t = l for the scan
    const int b    = blockIdx.x;
    const int lane = t & 31;
    const int w    = t >> 5;

    // ---- load index for site l = t ----
    int v;
    if (g_is_int64) {
        v = (int)((const long long*)idx_raw)[(size_t)b * L_SZ + t];
    } else {
        v = ((const int*)idx_raw)[b * L_SZ + t];
    }

    // ---- exclusive prefix popcount of bit0 (up) / bit1 (dn) over l ----
    unsigned bu = __ballot_sync(0xffffffffu, v & 1);
    unsigned bd = __ballot_sync(0xffffffffu, v & 2);
    unsigned mlt = (1u << lane) - 1u;
    int nup = __popc(bu & mlt);
    int ndn = __popc(bd & mlt);
    if (w == 0 && lane == 31) {          // warp0 totals for warp1's offset
        wu = nup + (v & 1);
        wd = ndn + ((v >> 1) & 1);
    }
    __syncthreads();
    if (w == 1) { nup += wu; ndn += wd; }

    // per-site base offset (excludes the m term)
    offs[t] = v * IDX_STRIDE + t * L_STRIDE + nup * 65 + ndn;
    __syncthreads();

    // ---- gather + product: thread t handles column m = t ----
    const float* eb = eps + t * M_STRIDE;
    float p0 = 1.f, p1 = 1.f, p2 = 1.f, p3 = 1.f;
    #pragma unroll
    for (int l = 0; l < L_SZ; l += 4) {
        p0 *= __ldg(eb + offs[l + 0]);
        p1 *= __ldg(eb + offs[l + 1]);
        p2 *= __ldg(eb + offs[l + 2]);
        p3 *= __ldg(eb + offs[l + 3]);
    }
    float p = (p0 * p1) * (p2 * p3);

    // ---- sum over the 64 m-columns ----
    #pragma unroll
    for (int o = 16; o; o >>= 1) p += __shfl_xor_sync(0xffffffffu, p, o);
    if (t == 0) wsum0 = p;
    __syncthreads();
    if (t == 32) out[b] = wsum0 + p;
}

extern "C" void kernel_launch(void* const* d_in, const int* in_sizes, int n_in,
                              void* d_out, int out_size)
{
    const void*  idx = d_in[0];                 // indices (B,L) int32 or int64
    const float* eps = (const float*)d_in[1];   // epsilon (4,64,64,65,65) fp32
    float* out = (float*)d_out;

    int n = in_sizes[0];                        // 524288 elements
    int n_pairs = n / 2;                        // stay within first n words

    detect_reset_kernel<<<1, 1>>>();
    detect_kernel<<<(n_pairs + 255) / 256, 256>>>((const unsigned*)idx, n_pairs);
    seggps_kernel<<<B_SZ, 64>>>(idx, eps, out);
}

// round 2
// speedup vs baseline: 4.4905x; 4.4905x over previous
#include <cuda_runtime.h>

// SegGPS_66949950210076
// out[b] = sum_m prod_l eps[idx[b,l], m, l, nup[b,l], ndn[b,l]]
// B=8192, L=64, M=64, LOCAL_DIM=4, eps shape (4,64,64,65,65) fp32.
//
// Strategy: only the nup<=l, ndn<=l region of eps is reachable
// (prefix counts over l sites). Re-layout that region each launch into
//   T[cell(l,nup,ndn)][idx][m]   (m contiguous, 256B per (cell,idx))
// cells = sum_{l}(l+1)^2 = 89440  -> T = 91.6 MB, fits in L2.
// Gather then reads one fully-used 256B block per (b,l) instead of
// 64 scattered 32B sectors (8x sector-traffic reduction).

#define B_SZ 8192
#define L_SZ 64
#define IDX_STRIDE 17305600   // M*L*65*65
#define M_STRIDE   270400     // L*65*65
#define L_STRIDE   4225       // 65*65
#define CELLS      89440      // sum_{k=1..64} k^2
#define T_ELEMS    (CELLS * 256)

__device__ float g_T[T_ELEMS];          // 91.6 MB scratch (static: no alloc)
__device__ int   g_is_int64;

__device__ __forceinline__ int cell_off(int l) {
    // sum_{j=1..l} j^2 = l(l+1)(2l+1)/6
    return l * (l + 1) * (2 * l + 1) / 6;
}

__global__ void detect_reset_kernel() { g_is_int64 = 1; }

// Indices are logically int64 in the reference, but JAX default (x64 off)
// produces int32. Under int64 LE every odd 32-bit word is 0 (values < 4);
// under int32 that is astronomically unlikely over 262k samples. Scan only
// the first n 32-bit words (in-bounds under either layout).
__global__ void detect_kernel(const unsigned* __restrict__ w, int n_pairs) {
    int i = blockIdx.x * blockDim.x + threadIdx.x;
    if (i < n_pairs && w[2 * i + 1] != 0u) g_is_int64 = 0;
}

// One CTA per (l, nup, idx). smem-tiled m<->ndn transpose so both the
// source read (along ndn) and the dest write (along m) are coalesced.
__global__ __launch_bounds__(256) void transpose_kernel(const float* __restrict__ eps) {
    const int l = blockIdx.x, nup = blockIdx.y, idx = blockIdx.z;
    if (nup > l) return;
    const int nv = l + 1;                       // valid ndn count

    __shared__ float sm[64][65];                // [m][ndn], pad -> conflict-free
    const int tid = threadIdx.x;
    const int c  = tid & 63;                    // read: ndn ; write: m
    const int r4 = tid >> 6;                    // row sub-block 0..3

    const float* src = eps + idx * IDX_STRIDE + l * L_STRIDE + nup * 65;
    if (c < nv) {
        #pragma unroll
        for (int mb = 0; mb < 64; mb += 4) {
            int m = mb + r4;
            sm[m][c] = src[m * M_STRIDE + c];   // coalesced along ndn
        }
    }
    __syncthreads();

    float* dst = g_T + (cell_off(l) + nup * nv) * 256 + idx * 64;
    #pragma unroll
    for (int nb = 0; nb < 64; nb += 4) {
        int ndn = nb + r4;
        if (ndn < nv)
            dst[ndn * 256 + c] = sm[c][ndn];    // coalesced along m (256B)
    }
}

__global__ __launch_bounds__(64) void seggps_kernel(
    const void* __restrict__ idx_raw,
    float*      __restrict__ out)
{
    __shared__ int   offs[L_SZ];
    __shared__ int   wu, wd;
    __shared__ float wsum0;

    const int t    = threadIdx.x;   // t = l for the scan phase, t = m for gather
    const int b    = blockIdx.x;
    const int lane = t & 31;
    const int w    = t >> 5;

    // ---- index for site l = t ----
    int v;
    if (g_is_int64) v = (int)((const long long*)idx_raw)[(size_t)b * L_SZ + t];
    else            v = ((const int*)idx_raw)[b * L_SZ + t];

    // ---- exclusive prefix popcount of bit0 (up) / bit1 (dn) over l ----
    unsigned bu = __ballot_sync(0xffffffffu, v & 1);
    unsigned bd = __ballot_sync(0xffffffffu, v & 2);
    unsigned mlt = (1u << lane) - 1u;
    int nup = __popc(bu & mlt);
    int ndn = __popc(bd & mlt);
    if (w == 0 && lane == 31) {
        wu = nup + (v & 1);
        wd = ndn + ((v >> 1) & 1);
    }
    __syncthreads();
    if (w == 1) { nup += wu; ndn += wd; }

    // float offset of the 256B (cell,idx) block for site t
    offs[t] = (cell_off(t) + nup * (t + 1) + ndn) * 256 + v * 64;
    __syncthreads();

    // ---- gather + product: thread t handles column m = t ----
    float p0 = 1.f, p1 = 1.f, p2 = 1.f, p3 = 1.f;
    #pragma unroll
    for (int l = 0; l < L_SZ; l += 4) {
        p0 *= __ldg(g_T + offs[l + 0] + t);
        p1 *= __ldg(g_T + offs[l + 1] + t);
        p2 *= __ldg(g_T + offs[l + 2] + t);
        p3 *= __ldg(g_T + offs[l + 3] + t);
    }
    float p = (p0 * p1) * (p2 * p3);

    // ---- sum over the 64 m-columns ----
    #pragma unroll
    for (int o = 16; o; o >>= 1) p += __shfl_xor_sync(0xffffffffu, p, o);
    if (t == 0) wsum0 = p;
    __syncthreads();
    if (t == 32) out[b] = wsum0 + p;
}

extern "C" void kernel_launch(void* const* d_in, const int* in_sizes, int n_in,
                              void* d_out, int out_size)
{
    const void*  idx = d_in[0];                 // indices (B,L) int32 or int64
    const float* eps = (const float*)d_in[1];   // epsilon (4,64,64,65,65) fp32
    float* out = (float*)d_out;

    int n = in_sizes[0];                        // 524288 elements
    int n_pairs = n / 2;

    detect_reset_kernel<<<1, 1>>>();
    detect_kernel<<<(n_pairs + 255) / 256, 256>>>((const unsigned*)idx, n_pairs);
    transpose_kernel<<<dim3(64, 64, 4), 256>>>(eps);
    seggps_kernel<<<B_SZ, 64>>>(idx, out);
}

// round 3
// speedup vs baseline: 4.4931x; 1.0006x over previous
#include <cuda_runtime.h>

// SegGPS_66949950210076
// out[b] = sum_m prod_l eps[idx[b,l], m, l, nup[b,l], ndn[b,l]]
// B=8192, L=64, M=64, LOCAL_DIM=4, eps (4,64,64,65,65) fp32.
//
// R3: demand-driven transpose. Only cells (l,nup,ndn,idx) actually touched
// by this batch (~18% of the 89,440-cell triangle) are re-laid-out into
//   T[cell][idx][m]  (m contiguous, 256B blocks, L2-resident)
// Flags computed per launch from the indices; transpose reads/writes are
// predicated on them. Gather: warp-per-batch, float2 (2 m-columns/lane).

#define B_SZ   8192
#define L_SZ   64
#define IDX_STRIDE 17305600   // M*L*65*65
#define M_STRIDE   270400     // L*65*65
#define L_STRIDE   4225       // 65*65
#define CELLS  89440          // sum_{k=1..64} k^2
#define T_ELEMS (CELLS * 256)

__device__ float         g_T[T_ELEMS];        // 91.6 MB scratch (static)
__device__ unsigned char g_flags[4][CELLS];   // touched-cell flags (358 KB)
__device__ int           g_is_int64;

__device__ __forceinline__ int cell_off(int l) {
    return l * (l + 1) * (2 * l + 1) / 6;     // sum_{j=1..l} j^2
}

// ---- clear flags + reset dtype detector (one kernel) ----
__global__ __launch_bounds__(256) void clear_kernel() {
    int i = blockIdx.x * blockDim.x + threadIdx.x;
    if (i < CELLS) ((unsigned*)g_flags)[i] = 0u;   // 4*CELLS bytes = CELLS words
    if (i == 0) g_is_int64 = 1;
}

// Indices are logically int64 (ref) but JAX x64-off emits int32. Under int64
// LE every odd 32-bit word is 0 (values < 4); under int32 that's impossible
// over 262k samples. Scan only the first n words (in-bounds either way).
__global__ void detect_kernel(const unsigned* __restrict__ w, int n_pairs) {
    int i = blockIdx.x * blockDim.x + threadIdx.x;
    if (i < n_pairs && w[2 * i + 1] != 0u) g_is_int64 = 0;
}

// Per-warp scan of one batch: two ballots cover all 64 sites.
// Returns the two cell-local offsets; also yields v0,v1.
__device__ __forceinline__ void scan_batch(
    const void* idx_raw, int b, int lane,
    int& v0, int& v1, int& cell0, int& cell1)
{
    if (g_is_int64) {
        const long long* p = (const long long*)idx_raw + (size_t)b * L_SZ;
        v0 = (int)p[lane];  v1 = (int)p[lane + 32];
    } else {
        const int* p = (const int*)idx_raw + b * L_SZ;
        v0 = p[lane];  v1 = p[lane + 32];
    }
    unsigned bu0 = __ballot_sync(0xffffffffu, v0 & 1);
    unsigned bd0 = __ballot_sync(0xffffffffu, v0 & 2);
    unsigned bu1 = __ballot_sync(0xffffffffu, v1 & 1);
    unsigned bd1 = __ballot_sync(0xffffffffu, v1 & 2);
    unsigned mlt = (1u << lane) - 1u;
    int nup0 = __popc(bu0 & mlt),               ndn0 = __popc(bd0 & mlt);
    int nup1 = __popc(bu0) + __popc(bu1 & mlt), ndn1 = __popc(bd0) + __popc(bd1 & mlt);
    int l0 = lane, l1 = lane + 32;
    cell0 = cell_off(l0) + nup0 * (l0 + 1) + ndn0;
    cell1 = cell_off(l1) + nup1 * (l1 + 1) + ndn1;
}

// ---- mark touched cells ----
__global__ __launch_bounds__(256) void flag_kernel(const void* __restrict__ idx_raw) {
    int lane = threadIdx.x & 31;
    int b = blockIdx.x * 8 + (threadIdx.x >> 5);
    int v0, v1, c0, c1;
    scan_batch(idx_raw, b, lane, v0, v1, c0, c1);
    g_flags[v0][c0] = 1;
    g_flags[v1][c1] = 1;
}

// ---- demand-driven transpose: CTA per (l, nup, idx) ----
__global__ __launch_bounds__(256) void transpose_kernel(const float* __restrict__ eps) {
    const int l = blockIdx.x, nup = blockIdx.y, idx = blockIdx.z;
    if (nup > l) return;
    const int nv = l + 1;

    __shared__ float         sm[64][65];
    __shared__ unsigned char sflag[64];

    const int tid = threadIdx.x;
    const int c  = tid & 63;      // read phase: ndn ; write phase: m
    const int r4 = tid >> 6;

    int f = 0;
    if (r4 == 0 && c < nv) {
        f = g_flags[idx][cell_off(l) + nup * nv + c];
        sflag[c] = (unsigned char)f;
    }
    if (!__syncthreads_or(f)) return;            // nothing touched here

    const bool colf = (c < nv) && sflag[c];
    const float* src = eps + idx * IDX_STRIDE + l * L_STRIDE + nup * 65;
    if (colf) {
        #pragma unroll
        for (int mb = 0; mb < 64; mb += 4) {
            int m = mb + r4;
            sm[m][c] = src[m * M_STRIDE + c];    // only flagged ndn columns fetch
        }
    }
    __syncthreads();

    float* dst = g_T + (cell_off(l) + nup * nv) * 256 + idx * 64;
    #pragma unroll
    for (int nb = 0; nb < 64; nb += 4) {
        int ndn = nb + r4;
        if (ndn < nv && sflag[ndn])
            dst[ndn * 256 + c] = sm[c][ndn];     // 256B coalesced, flagged only
    }
}

// ---- gather: warp per batch, float2 per lane (m = 2*lane, 2*lane+1) ----
__global__ __launch_bounds__(256) void seggps_kernel(
    const void* __restrict__ idx_raw,
    float*      __restrict__ out)
{
    __shared__ int soffs[8][64];

    const int lane = threadIdx.x & 31;
    const int w    = threadIdx.x >> 5;
    const int b    = blockIdx.x * 8 + w;

    int v0, v1, c0, c1;
    scan_batch(idx_raw, b, lane, v0, v1, c0, c1);
    soffs[w][lane]      = c0 * 256 + v0 * 64;
    soffs[w][lane + 32] = c1 * 256 + v1 * 64;
    __syncwarp();

    float p0x = 1.f, p0y = 1.f, p1x = 1.f, p1y = 1.f;
    float p2x = 1.f, p2y = 1.f, p3x = 1.f, p3y = 1.f;
    #pragma unroll
    for (int l = 0; l < L_SZ; l += 4) {
        float2 a = __ldg((const float2*)(g_T + soffs[w][l + 0]) + lane);
        float2 b2 = __ldg((const float2*)(g_T + soffs[w][l + 1]) + lane);
        float2 c = __ldg((const float2*)(g_T + soffs[w][l + 2]) + lane);
        float2 d = __ldg((const float2*)(g_T + soffs[w][l + 3]) + lane);
        p0x *= a.x;  p0y *= a.y;
        p1x *= b2.x; p1y *= b2.y;
        p2x *= c.x;  p2y *= c.y;
        p3x *= d.x;  p3y *= d.y;
    }
    float s = (p0x * p1x) * (p2x * p3x) + (p0y * p1y) * (p2y * p3y);

    #pragma unroll
    for (int o = 16; o; o >>= 1) s += __shfl_xor_sync(0xffffffffu, s, o);
    if (lane == 0) out[b] = s;
}

extern "C" void kernel_launch(void* const* d_in, const int* in_sizes, int n_in,
                              void* d_out, int out_size)
{
    const void*  idx = d_in[0];                 // indices (B,L) int32 or int64
    const float* eps = (const float*)d_in[1];   // epsilon fp32
    float* out = (float*)d_out;

    int n = in_sizes[0];                        // 524288
    int n_pairs = n / 2;

    clear_kernel<<<(CELLS + 255) / 256, 256>>>();
    detect_kernel<<<(n_pairs + 255) / 256, 256>>>((const unsigned*)idx, n_pairs);
    flag_kernel<<<B_SZ / 8, 256>>>(idx);
    transpose_kernel<<<dim3(64, 64, 4), 256>>>(eps);
    seggps_kernel<<<B_SZ / 8, 256>>>(idx, out);
}